// round 2
// baseline (speedup 1.0000x reference)
#include <cuda_runtime.h>

#define N_NODES 50000
#define F       64
#define HID     256
#define E_EDGES 800000

// Scratch (no cudaMalloc allowed)
__device__ float g_M[F * F];        // W1 @ W2  (64x64)
__device__ float g_c[F];            // b1 @ W2 + b2
__device__ float g_y[N_NODES * F];  // x @ M    (12.8 MB, L2-resident)

// ---------------------------------------------------------------------------
// Kernel A: M = W1 @ W2, c = b1 @ W2 + b2   (tiny: 1 MFLOP)
// ---------------------------------------------------------------------------
__global__ void prep_kernel(const float* __restrict__ W1, const float* __restrict__ b1,
                            const float* __restrict__ W2, const float* __restrict__ b2) {
    int idx = blockIdx.x * blockDim.x + threadIdx.x;
    if (idx < F * F) {
        int i = idx >> 6;
        int j = idx & 63;
        float acc = 0.f;
        #pragma unroll 8
        for (int k = 0; k < HID; k++)
            acc += W1[i * HID + k] * W2[k * F + j];
        g_M[idx] = acc;
    } else if (idx < F * F + F) {
        int j = idx - F * F;
        float acc = b2[j];
        #pragma unroll 8
        for (int k = 0; k < HID; k++)
            acc += b1[k] * W2[k * F + j];
        g_c[j] = acc;
    }
}

// ---------------------------------------------------------------------------
// Kernel B: y = x @ M  (stored to g_y), and out = (1+eps)*y + c (self term)
// One thread per node row; M staged in shared memory (broadcast reads).
// ---------------------------------------------------------------------------
__global__ __launch_bounds__(256) void gemm_kernel(const float* __restrict__ x,
                                                   const float* __restrict__ eps,
                                                   float* __restrict__ out) {
    __shared__ float Ms[F * F];
    __shared__ float cs[F];
    int tid = threadIdx.x;
    #pragma unroll
    for (int i = tid; i < F * F; i += 256) Ms[i] = g_M[i];
    if (tid < F) cs[tid] = g_c[tid];
    __syncthreads();

    int row = blockIdx.x * 256 + tid;
    if (row >= N_NODES) return;

    float acc[F];
    #pragma unroll
    for (int j = 0; j < F; j++) acc[j] = 0.f;

    const float4* xr = reinterpret_cast<const float4*>(x + (size_t)row * F);
    #pragma unroll
    for (int k4 = 0; k4 < F / 4; k4++) {
        float4 xv = __ldg(xr + k4);
        const float* m = &Ms[(k4 * 4) * F];
        #pragma unroll
        for (int j = 0; j < F; j++) {
            acc[j] += xv.x * m[j]
                    + xv.y * m[j + F]
                    + xv.z * m[j + 2 * F]
                    + xv.w * m[j + 3 * F];
        }
    }

    float e1 = 1.0f + __ldg(eps);
    float4* yr = reinterpret_cast<float4*>(g_y + (size_t)row * F);
    float4* orow = reinterpret_cast<float4*>(out + (size_t)row * F);
    #pragma unroll
    for (int j4 = 0; j4 < F / 4; j4++) {
        float4 v;
        v.x = acc[j4 * 4 + 0];
        v.y = acc[j4 * 4 + 1];
        v.z = acc[j4 * 4 + 2];
        v.w = acc[j4 * 4 + 3];
        yr[j4] = v;
        float4 o;
        o.x = e1 * v.x + cs[j4 * 4 + 0];
        o.y = e1 * v.y + cs[j4 * 4 + 1];
        o.z = e1 * v.z + cs[j4 * 4 + 2];
        o.w = e1 * v.w + cs[j4 * 4 + 3];
        orow[j4] = o;
    }
}

// ---------------------------------------------------------------------------
// Kernel C: edge scatter: out[dst] += y[src]  via red.global.add.v4.f32
// 16 threads per edge (one float4 lane each).
// ---------------------------------------------------------------------------
__global__ __launch_bounds__(256) void scatter_kernel(const int* __restrict__ src,
                                                      const int* __restrict__ dst,
                                                      float* __restrict__ out) {
    int idx = blockIdx.x * blockDim.x + threadIdx.x;
    int e = idx >> 4;
    int j = idx & 15;
    if (e >= E_EDGES) return;
    int s = __ldg(src + e);
    int d = __ldg(dst + e);
    float4 v = __ldg(reinterpret_cast<const float4*>(g_y + (size_t)s * F) + j);
    float* p = out + (size_t)d * F + j * 4;
    asm volatile("red.global.add.v4.f32 [%0], {%1,%2,%3,%4};"
                 :: "l"(p), "f"(v.x), "f"(v.y), "f"(v.z), "f"(v.w)
                 : "memory");
}

// ---------------------------------------------------------------------------
extern "C" void kernel_launch(void* const* d_in, const int* in_sizes, int n_in,
                              void* d_out, int out_size) {
    const float* x   = (const float*)d_in[0];
    const float* W1  = (const float*)d_in[1];
    const float* b1  = (const float*)d_in[2];
    const float* W2  = (const float*)d_in[3];
    const float* b2  = (const float*)d_in[4];
    const float* eps = (const float*)d_in[5];
    const int*   src = (const int*)d_in[6];
    const int*   dst = (const int*)d_in[7];
    float* out = (float*)d_out;

    prep_kernel<<<(F * F + F + 255) / 256, 256>>>(W1, b1, W2, b2);
    gemm_kernel<<<(N_NODES + 255) / 256, 256>>>(x, eps, out);
    scatter_kernel<<<((long long)E_EDGES * 16 + 255) / 256, 256>>>(src, dst, out);
}

// round 3
// speedup vs baseline: 1.1747x; 1.1747x over previous
#include <cuda_runtime.h>

#define N_NODES 50000
#define F       64
#define HID     256
#define E_EDGES 800000
#define CAP     80          // bucket capacity per node (mean degree 16)
#define OVF_MAX 8192

// Scratch (no cudaMalloc allowed)
__device__ float g_M[F * F];            // W1 @ W2  (64x64), row-major [k][j]
__device__ float g_c[F];                // b1 @ W2 + b2
__device__ float g_y[N_NODES * F];      // x @ M    (12.8 MB, L2-resident)
__device__ int   g_count[N_NODES];      // per-dst degree counter
__device__ int   g_bucket[N_NODES * CAP]; // per-dst src lists (padded)
__device__ int   g_over;                // overflow edge count
__device__ int   g_osrc[OVF_MAX];
__device__ int   g_odst[OVF_MAX];

// ---------------------------------------------------------------------------
// Kernel A: M = W1 @ W2, c = b1 @ W2 + b2. One warp per output element,
// 32-way split-K + shfl reduce. Also zeroes g_count / g_over.
// 4160 outputs -> 4160 warps -> 520 blocks of 256.
// ---------------------------------------------------------------------------
__global__ __launch_bounds__(256) void prep_kernel(const float* __restrict__ W1,
                                                   const float* __restrict__ b1,
                                                   const float* __restrict__ W2,
                                                   const float* __restrict__ b2) {
    int gtid = blockIdx.x * 256 + threadIdx.x;
    // side job: zero counters
    if (gtid < N_NODES) g_count[gtid] = 0;
    if (gtid == 0) g_over = 0;

    int wid  = gtid >> 5;     // global warp id = output element id
    int lane = gtid & 31;
    if (wid >= F * F + F) return;

    float acc = 0.f;
    if (wid < F * F) {
        int i = wid >> 6;
        int j = wid & 63;
        #pragma unroll
        for (int t = 0; t < HID / 32; t++) {
            int k = lane + t * 32;
            acc += __ldg(W1 + i * HID + k) * __ldg(W2 + k * F + j);
        }
        #pragma unroll
        for (int off = 16; off > 0; off >>= 1)
            acc += __shfl_down_sync(0xffffffffu, acc, off);
        if (lane == 0) g_M[wid] = acc;
    } else {
        int j = wid - F * F;
        #pragma unroll
        for (int t = 0; t < HID / 32; t++) {
            int k = lane + t * 32;
            acc += __ldg(b1 + k) * __ldg(W2 + k * F + j);
        }
        #pragma unroll
        for (int off = 16; off > 0; off >>= 1)
            acc += __shfl_down_sync(0xffffffffu, acc, off);
        if (lane == 0) g_c[j] = acc + __ldg(b2 + j);
    }
}

// ---------------------------------------------------------------------------
// Kernel B: bucket fill. pos = count[dst]++ ; bucket[dst*CAP+pos] = src
// Overflow (should never happen for Poisson(16)) goes to a side list.
// ---------------------------------------------------------------------------
__global__ __launch_bounds__(256) void fill_kernel(const int* __restrict__ src,
                                                   const int* __restrict__ dst) {
    int e = blockIdx.x * 256 + threadIdx.x;
    if (e >= E_EDGES) return;
    int d = __ldg(dst + e);
    int s = __ldg(src + e);
    int pos = atomicAdd(&g_count[d], 1);
    if (pos < CAP) {
        g_bucket[d * CAP + pos] = s;
    } else {
        int o = atomicAdd(&g_over, 1);
        if (o < OVF_MAX) { g_osrc[o] = s; g_odst[o] = d; }
    }
}

// ---------------------------------------------------------------------------
// Kernel C: y = x @ M. One thread per node row; M broadcast from shared.
// ---------------------------------------------------------------------------
__global__ __launch_bounds__(256) void gemm_kernel(const float* __restrict__ x) {
    __shared__ float Ms[F * F];
    int tid = threadIdx.x;
    #pragma unroll
    for (int i = tid; i < F * F; i += 256) Ms[i] = g_M[i];
    __syncthreads();

    int row = blockIdx.x * 256 + tid;
    if (row >= N_NODES) return;

    float acc[F];
    #pragma unroll
    for (int j = 0; j < F; j++) acc[j] = 0.f;

    const float4* xr = reinterpret_cast<const float4*>(x + (size_t)row * F);
    #pragma unroll
    for (int k4 = 0; k4 < F / 4; k4++) {
        float4 xv = __ldg(xr + k4);
        const float* m = &Ms[(k4 * 4) * F];
        #pragma unroll
        for (int j = 0; j < F; j++) {
            acc[j] += xv.x * m[j]
                    + xv.y * m[j + F]
                    + xv.z * m[j + 2 * F]
                    + xv.w * m[j + 3 * F];
        }
    }

    float4* yr = reinterpret_cast<float4*>(g_y + (size_t)row * F);
    #pragma unroll
    for (int j4 = 0; j4 < F / 4; j4++) {
        float4 v;
        v.x = acc[j4 * 4 + 0];
        v.y = acc[j4 * 4 + 1];
        v.z = acc[j4 * 4 + 2];
        v.w = acc[j4 * 4 + 3];
        yr[j4] = v;
    }
}

// ---------------------------------------------------------------------------
// Kernel D: per-node reduce. 16 threads per node, one float4 chunk each.
// out[d] = sum_{s in bucket[d]} y[s] + (1+eps)*y[d] + c
// ---------------------------------------------------------------------------
__global__ __launch_bounds__(256) void reduce_kernel(const float* __restrict__ eps,
                                                     float* __restrict__ out) {
    int tid  = threadIdx.x;
    int node = blockIdx.x * 16 + (tid >> 4);
    int j4   = tid & 15;
    if (node >= N_NODES) return;

    int deg = g_count[node];
    if (deg > CAP) deg = CAP;
    const int* bk = g_bucket + (size_t)node * CAP;

    float4 acc = make_float4(0.f, 0.f, 0.f, 0.f);
    int k = 0;
    // unroll-by-2 to expose MLP on the index->gather chain
    for (; k + 1 < deg; k += 2) {
        int s0 = __ldg(bk + k);
        int s1 = __ldg(bk + k + 1);
        float4 v0 = __ldg(reinterpret_cast<const float4*>(g_y + (size_t)s0 * F) + j4);
        float4 v1 = __ldg(reinterpret_cast<const float4*>(g_y + (size_t)s1 * F) + j4);
        acc.x += v0.x + v1.x;
        acc.y += v0.y + v1.y;
        acc.z += v0.z + v1.z;
        acc.w += v0.w + v1.w;
    }
    if (k < deg) {
        int s0 = __ldg(bk + k);
        float4 v0 = __ldg(reinterpret_cast<const float4*>(g_y + (size_t)s0 * F) + j4);
        acc.x += v0.x; acc.y += v0.y; acc.z += v0.z; acc.w += v0.w;
    }

    float e1 = 1.0f + __ldg(eps);
    float4 yd = __ldg(reinterpret_cast<const float4*>(g_y + (size_t)node * F) + j4);
    float4 c  = reinterpret_cast<const float4*>(g_c)[j4];

    float4 o;
    o.x = acc.x + e1 * yd.x + c.x;
    o.y = acc.y + e1 * yd.y + c.y;
    o.z = acc.z + e1 * yd.z + c.z;
    o.w = acc.w + e1 * yd.w + c.w;
    reinterpret_cast<float4*>(out + (size_t)node * F)[j4] = o;
}

// ---------------------------------------------------------------------------
// Kernel E: overflow fixup (normally 0 edges). red.add into finished out.
// ---------------------------------------------------------------------------
__global__ __launch_bounds__(256) void overflow_kernel(float* __restrict__ out) {
    int n = g_over;
    if (n > OVF_MAX) n = OVF_MAX;
    int total = n * 16;
    for (int idx = blockIdx.x * 256 + threadIdx.x; idx < total;
         idx += gridDim.x * 256) {
        int e = idx >> 4;
        int j4 = idx & 15;
        int s = g_osrc[e];
        int d = g_odst[e];
        float4 v = __ldg(reinterpret_cast<const float4*>(g_y + (size_t)s * F) + j4);
        float* p = out + (size_t)d * F + j4 * 4;
        asm volatile("red.global.add.v4.f32 [%0], {%1,%2,%3,%4};"
                     :: "l"(p), "f"(v.x), "f"(v.y), "f"(v.z), "f"(v.w)
                     : "memory");
    }
}

// ---------------------------------------------------------------------------
extern "C" void kernel_launch(void* const* d_in, const int* in_sizes, int n_in,
                              void* d_out, int out_size) {
    const float* x   = (const float*)d_in[0];
    const float* W1  = (const float*)d_in[1];
    const float* b1  = (const float*)d_in[2];
    const float* W2  = (const float*)d_in[3];
    const float* b2  = (const float*)d_in[4];
    const float* eps = (const float*)d_in[5];
    const int*   src = (const int*)d_in[6];
    const int*   dst = (const int*)d_in[7];
    float* out = (float*)d_out;

    prep_kernel<<<520, 256>>>(W1, b1, W2, b2);
    fill_kernel<<<(E_EDGES + 255) / 256, 256>>>(src, dst);
    gemm_kernel<<<(N_NODES + 255) / 256, 256>>>(x);
    reduce_kernel<<<(N_NODES + 15) / 16, 256>>>(eps, out);
    overflow_kernel<<<16, 256>>>(out);
}

// round 4
// speedup vs baseline: 1.4474x; 1.2322x over previous
#include <cuda_runtime.h>

#define N_NODES 50000
#define F       64
#define HID     256
#define E_EDGES 800000
#define CAP     80
#define OVF_MAX 8192
#define GEMM_BLOCKS 196   // ceil(50000/256)
#define FILL_BLOCKS 782   // ceil(800000/4/256)

// Scratch (no cudaMalloc allowed)
__device__ float g_M[F * F];              // W1 @ W2 (64x64), [k][j]
__device__ float g_c[F];                  // b1 @ W2 + b2
__device__ float g_y[N_NODES * F];        // x @ M
__device__ int   g_count[N_NODES];
__device__ int   g_bucket[N_NODES * CAP];
__device__ int   g_over;
__device__ int   g_osrc[OVF_MAX];
__device__ int   g_odst[OVF_MAX];

// ---------------------------------------------------------------------------
// Kernel A: M = W1@W2, c = b1@W2+b2 (warp per output, split-K) + zero counters
// ---------------------------------------------------------------------------
__global__ __launch_bounds__(256) void prep_kernel(const float* __restrict__ W1,
                                                   const float* __restrict__ b1,
                                                   const float* __restrict__ W2,
                                                   const float* __restrict__ b2) {
    int gtid = blockIdx.x * 256 + threadIdx.x;
    if (gtid < N_NODES) g_count[gtid] = 0;
    if (gtid == 0) g_over = 0;

    int wid  = gtid >> 5;
    int lane = gtid & 31;
    if (wid >= F * F + F) return;

    float acc = 0.f;
    if (wid < F * F) {
        int i = wid >> 6;
        int j = wid & 63;
        #pragma unroll
        for (int t = 0; t < HID / 32; t++) {
            int k = lane + t * 32;
            acc += __ldg(W1 + i * HID + k) * __ldg(W2 + k * F + j);
        }
        #pragma unroll
        for (int off = 16; off > 0; off >>= 1)
            acc += __shfl_down_sync(0xffffffffu, acc, off);
        if (lane == 0) g_M[wid] = acc;
    } else {
        int j = wid - F * F;
        #pragma unroll
        for (int t = 0; t < HID / 32; t++) {
            int k = lane + t * 32;
            acc += __ldg(b1 + k) * __ldg(W2 + k * F + j);
        }
        #pragma unroll
        for (int off = 16; off > 0; off >>= 1)
            acc += __shfl_down_sync(0xffffffffu, acc, off);
        if (lane == 0) g_c[j] = acc + __ldg(b2 + j);
    }
}

// ---------------------------------------------------------------------------
// Kernel B (fused): blocks [0,GEMM_BLOCKS) do y = x@M, the rest do bucket fill.
// gemm: LDS.128 broadcast loads of M, 16 float4 accumulators per thread.
// fill: 4 edges per thread via int4 loads.
// ---------------------------------------------------------------------------
__global__ __launch_bounds__(256) void mid_kernel(const float* __restrict__ x,
                                                  const int* __restrict__ src,
                                                  const int* __restrict__ dst) {
    if (blockIdx.x < GEMM_BLOCKS) {
        __shared__ float4 Ms4[F * (F / 4)];   // [row][j4]
        int tid = threadIdx.x;
        const float4* Mg = reinterpret_cast<const float4*>(g_M);
        #pragma unroll
        for (int i = tid; i < F * (F / 4); i += 256) Ms4[i] = Mg[i];
        __syncthreads();

        int row = blockIdx.x * 256 + tid;
        if (row >= N_NODES) return;

        float4 acc[F / 4];
        #pragma unroll
        for (int j4 = 0; j4 < F / 4; j4++) acc[j4] = make_float4(0.f, 0.f, 0.f, 0.f);

        const float4* xr = reinterpret_cast<const float4*>(x + (size_t)row * F);
        #pragma unroll
        for (int k4 = 0; k4 < F / 4; k4++) {
            float4 xv = __ldg(xr + k4);
            #pragma unroll
            for (int kk = 0; kk < 4; kk++) {
                float xs = (kk == 0) ? xv.x : (kk == 1) ? xv.y : (kk == 2) ? xv.z : xv.w;
                const float4* m = &Ms4[(k4 * 4 + kk) * (F / 4)];
                #pragma unroll
                for (int j4 = 0; j4 < F / 4; j4++) {
                    float4 mv = m[j4];
                    acc[j4].x += xs * mv.x;
                    acc[j4].y += xs * mv.y;
                    acc[j4].z += xs * mv.z;
                    acc[j4].w += xs * mv.w;
                }
            }
        }

        float4* yr = reinterpret_cast<float4*>(g_y + (size_t)row * F);
        #pragma unroll
        for (int j4 = 0; j4 < F / 4; j4++) yr[j4] = acc[j4];
    } else {
        int t = (blockIdx.x - GEMM_BLOCKS) * 256 + threadIdx.x;   // 4 edges each
        int e4 = t * 4;
        if (e4 >= E_EDGES) return;
        int4 s4 = __ldg(reinterpret_cast<const int4*>(src + e4));
        int4 d4 = __ldg(reinterpret_cast<const int4*>(dst + e4));
        #pragma unroll
        for (int q = 0; q < 4; q++) {
            int s = (q == 0) ? s4.x : (q == 1) ? s4.y : (q == 2) ? s4.z : s4.w;
            int d = (q == 0) ? d4.x : (q == 1) ? d4.y : (q == 2) ? d4.z : d4.w;
            int pos = atomicAdd(&g_count[d], 1);
            if (pos < CAP) {
                g_bucket[d * CAP + pos] = s;
            } else {
                int o = atomicAdd(&g_over, 1);
                if (o < OVF_MAX) { g_osrc[o] = s; g_odst[o] = d; }
            }
        }
    }
}

// ---------------------------------------------------------------------------
// Kernel C: per-node reduce. 8 threads/node, 2 float4 chunks each, unroll-4.
// out[d] = sum_{s in bucket[d]} y[s] + (1+eps)*y[d] + c. Overflow inline.
// ---------------------------------------------------------------------------
__global__ __launch_bounds__(256) void reduce_kernel(const float* __restrict__ eps,
                                                     float* __restrict__ out) {
    int tid  = threadIdx.x;
    int node = blockIdx.x * 32 + (tid >> 3);
    int j    = tid & 7;                // chunks j and j+8
    if (node >= N_NODES) return;

    int deg_raw = g_count[node];
    int deg = deg_raw > CAP ? CAP : deg_raw;
    const int* bk = g_bucket + (size_t)node * CAP;

    float4 accA = make_float4(0.f, 0.f, 0.f, 0.f);
    float4 accB = make_float4(0.f, 0.f, 0.f, 0.f);

    int k = 0;
    for (; k + 3 < deg; k += 4) {
        int s0 = __ldg(bk + k);
        int s1 = __ldg(bk + k + 1);
        int s2 = __ldg(bk + k + 2);
        int s3 = __ldg(bk + k + 3);
        const float4* r0 = reinterpret_cast<const float4*>(g_y + (size_t)s0 * F);
        const float4* r1 = reinterpret_cast<const float4*>(g_y + (size_t)s1 * F);
        const float4* r2 = reinterpret_cast<const float4*>(g_y + (size_t)s2 * F);
        const float4* r3 = reinterpret_cast<const float4*>(g_y + (size_t)s3 * F);
        float4 a0 = __ldg(r0 + j),     a1 = __ldg(r1 + j),
               a2 = __ldg(r2 + j),     a3 = __ldg(r3 + j);
        float4 b0 = __ldg(r0 + j + 8), b1 = __ldg(r1 + j + 8),
               b2 = __ldg(r2 + j + 8), b3 = __ldg(r3 + j + 8);
        accA.x += (a0.x + a1.x) + (a2.x + a3.x);
        accA.y += (a0.y + a1.y) + (a2.y + a3.y);
        accA.z += (a0.z + a1.z) + (a2.z + a3.z);
        accA.w += (a0.w + a1.w) + (a2.w + a3.w);
        accB.x += (b0.x + b1.x) + (b2.x + b3.x);
        accB.y += (b0.y + b1.y) + (b2.y + b3.y);
        accB.z += (b0.z + b1.z) + (b2.z + b3.z);
        accB.w += (b0.w + b1.w) + (b2.w + b3.w);
    }
    for (; k < deg; k++) {
        int s0 = __ldg(bk + k);
        const float4* r0 = reinterpret_cast<const float4*>(g_y + (size_t)s0 * F);
        float4 a0 = __ldg(r0 + j);
        float4 b0 = __ldg(r0 + j + 8);
        accA.x += a0.x; accA.y += a0.y; accA.z += a0.z; accA.w += a0.w;
        accB.x += b0.x; accB.y += b0.y; accB.z += b0.z; accB.w += b0.w;
    }

    if (deg_raw > CAP) {   // essentially never taken
        int ov = g_over; if (ov > OVF_MAX) ov = OVF_MAX;
        for (int i = 0; i < ov; i++) {
            if (g_odst[i] == node) {
                const float4* r0 = reinterpret_cast<const float4*>(g_y + (size_t)g_osrc[i] * F);
                float4 a0 = __ldg(r0 + j);
                float4 b0 = __ldg(r0 + j + 8);
                accA.x += a0.x; accA.y += a0.y; accA.z += a0.z; accA.w += a0.w;
                accB.x += b0.x; accB.y += b0.y; accB.z += b0.z; accB.w += b0.w;
            }
        }
    }

    float e1 = 1.0f + __ldg(eps);
    const float4* yd = reinterpret_cast<const float4*>(g_y + (size_t)node * F);
    float4 ya = __ldg(yd + j);
    float4 yb = __ldg(yd + j + 8);
    float4 ca = reinterpret_cast<const float4*>(g_c)[j];
    float4 cb = reinterpret_cast<const float4*>(g_c)[j + 8];

    float4 oa, ob;
    oa.x = accA.x + e1 * ya.x + ca.x;
    oa.y = accA.y + e1 * ya.y + ca.y;
    oa.z = accA.z + e1 * ya.z + ca.z;
    oa.w = accA.w + e1 * ya.w + ca.w;
    ob.x = accB.x + e1 * yb.x + cb.x;
    ob.y = accB.y + e1 * yb.y + cb.y;
    ob.z = accB.z + e1 * yb.z + cb.z;
    ob.w = accB.w + e1 * yb.w + cb.w;

    float4* orow = reinterpret_cast<float4*>(out + (size_t)node * F);
    orow[j]     = oa;
    orow[j + 8] = ob;
}

// ---------------------------------------------------------------------------
extern "C" void kernel_launch(void* const* d_in, const int* in_sizes, int n_in,
                              void* d_out, int out_size) {
    const float* x   = (const float*)d_in[0];
    const float* W1  = (const float*)d_in[1];
    const float* b1  = (const float*)d_in[2];
    const float* W2  = (const float*)d_in[3];
    const float* b2  = (const float*)d_in[4];
    const float* eps = (const float*)d_in[5];
    const int*   src = (const int*)d_in[6];
    const int*   dst = (const int*)d_in[7];
    float* out = (float*)d_out;

    prep_kernel<<<520, 256>>>(W1, b1, W2, b2);
    mid_kernel<<<GEMM_BLOCKS + FILL_BLOCKS, 256>>>(x, src, dst);
    reduce_kernel<<<(N_NODES + 31) / 32, 256>>>(eps, out);
}

// round 5
// speedup vs baseline: 1.4773x; 1.0207x over previous
#include <cuda_runtime.h>
#include <cuda_fp16.h>

#define N_NODES 50000
#define F       64
#define HID     256
#define E_EDGES 800000
#define CAP     80
#define OVF_MAX 8192
#define GEMM_BLOCKS 196   // ceil(50000/256)
#define FILL_BLOCKS 782   // ceil(800000/4/256)
#define PREP_ZBLK   196   // ceil(50000/256)

// Scratch (no cudaMalloc allowed)
__device__ float g_M[F * F];               // W1 @ W2 (64x64), [k][j]
__device__ float g_c[F];                   // b1 @ W2 + b2
__device__ float g_y[N_NODES * F];         // x @ M  (fp32, self term)
__device__ uint4 g_y16[N_NODES * (F / 8)]; // x @ M  (fp16, gather path)
__device__ int   g_count[N_NODES];
__device__ int   g_bucket[N_NODES * CAP];
__device__ int   g_over;
__device__ int   g_osrc[OVF_MAX];
__device__ int   g_odst[OVF_MAX];

// ---------------------------------------------------------------------------
// Kernel A: blocks 0..15  : M rows [4b,4b+4) via smem-tiled, j-coalesced GEMM
//           block  16     : c = b1@W2 + b2
//           blocks 17..   : zero g_count / g_over
// ---------------------------------------------------------------------------
__global__ __launch_bounds__(256) void prep_kernel(const float* __restrict__ W1,
                                                   const float* __restrict__ b1,
                                                   const float* __restrict__ W2,
                                                   const float* __restrict__ b2) {
    int b = blockIdx.x;
    int tid = threadIdx.x;

    if (b < 16) {
        __shared__ float W2s[64 * 64];   // one 64-k tile of W2
        __shared__ float W1s[4 * 64];    // 4 i-rows of the same k tile
        int ii = tid >> 6;               // 0..3
        int j  = tid & 63;
        int i  = b * 4 + ii;

        float acc = 0.f;
        #pragma unroll
        for (int kt = 0; kt < 4; kt++) {
            __syncthreads();
            const float4* ws = reinterpret_cast<const float4*>(W2 + kt * 64 * F);
            float4* wd = reinterpret_cast<float4*>(W2s);
            #pragma unroll
            for (int t = tid; t < 64 * 64 / 4; t += 256) wd[t] = __ldg(ws + t);
            // W1 tile: 4 rows x 64 k
            W1s[tid] = __ldg(W1 + (b * 4 + (tid >> 6)) * HID + kt * 64 + (tid & 63));
            __syncthreads();

            const float* w1r = &W1s[ii * 64];
            #pragma unroll
            for (int kk = 0; kk < 64; kk++)
                acc += w1r[kk] * W2s[kk * 64 + j];
        }
        g_M[i * F + j] = acc;
    } else if (b == 16) {
        if (tid < F) {
            int j = tid;
            float acc = __ldg(b2 + j);
            #pragma unroll 8
            for (int k = 0; k < HID; k++)
                acc += __ldg(b1 + k) * __ldg(W2 + k * F + j);
            g_c[j] = acc;
        }
    } else {
        int idx = (b - 17) * 256 + tid;
        if (idx < N_NODES) g_count[idx] = 0;
        if (idx == 0) g_over = 0;
    }
}

// ---------------------------------------------------------------------------
// Kernel B (fused): blocks [0,GEMM_BLOCKS) do y = x@M (fp32 + fp16 copies),
// the rest do bucket fill (4 edges/thread).
// ---------------------------------------------------------------------------
__global__ __launch_bounds__(256) void mid_kernel(const float* __restrict__ x,
                                                  const int* __restrict__ src,
                                                  const int* __restrict__ dst) {
    if (blockIdx.x < GEMM_BLOCKS) {
        __shared__ float4 Ms4[F * (F / 4)];   // [k][j4]
        int tid = threadIdx.x;
        const float4* Mg = reinterpret_cast<const float4*>(g_M);
        #pragma unroll
        for (int i = tid; i < F * (F / 4); i += 256) Ms4[i] = Mg[i];
        __syncthreads();

        int row = blockIdx.x * 256 + tid;
        if (row >= N_NODES) return;

        float4 acc[F / 4];
        #pragma unroll
        for (int j4 = 0; j4 < F / 4; j4++) acc[j4] = make_float4(0.f, 0.f, 0.f, 0.f);

        const float4* xr = reinterpret_cast<const float4*>(x + (size_t)row * F);
        #pragma unroll
        for (int k4 = 0; k4 < F / 4; k4++) {
            float4 xv = __ldg(xr + k4);
            #pragma unroll
            for (int kk = 0; kk < 4; kk++) {
                float xs = (kk == 0) ? xv.x : (kk == 1) ? xv.y : (kk == 2) ? xv.z : xv.w;
                const float4* m = &Ms4[(k4 * 4 + kk) * (F / 4)];
                #pragma unroll
                for (int j4 = 0; j4 < F / 4; j4++) {
                    float4 mv = m[j4];
                    acc[j4].x += xs * mv.x;
                    acc[j4].y += xs * mv.y;
                    acc[j4].z += xs * mv.z;
                    acc[j4].w += xs * mv.w;
                }
            }
        }

        float4* yr = reinterpret_cast<float4*>(g_y + (size_t)row * F);
        #pragma unroll
        for (int j4 = 0; j4 < F / 4; j4++) yr[j4] = acc[j4];

        uint4* y16r = g_y16 + (size_t)row * (F / 8);
        #pragma unroll
        for (int p = 0; p < F / 8; p++) {
            __half2 h0 = __floats2half2_rn(acc[2 * p].x,     acc[2 * p].y);
            __half2 h1 = __floats2half2_rn(acc[2 * p].z,     acc[2 * p].w);
            __half2 h2 = __floats2half2_rn(acc[2 * p + 1].x, acc[2 * p + 1].y);
            __half2 h3 = __floats2half2_rn(acc[2 * p + 1].z, acc[2 * p + 1].w);
            uint4 u;
            u.x = *reinterpret_cast<unsigned int*>(&h0);
            u.y = *reinterpret_cast<unsigned int*>(&h1);
            u.z = *reinterpret_cast<unsigned int*>(&h2);
            u.w = *reinterpret_cast<unsigned int*>(&h3);
            y16r[p] = u;
        }
    } else {
        int t = (blockIdx.x - GEMM_BLOCKS) * 256 + threadIdx.x;
        int e4 = t * 4;
        if (e4 >= E_EDGES) return;
        int4 s4 = __ldg(reinterpret_cast<const int4*>(src + e4));
        int4 d4 = __ldg(reinterpret_cast<const int4*>(dst + e4));
        #pragma unroll
        for (int q = 0; q < 4; q++) {
            int s = (q == 0) ? s4.x : (q == 1) ? s4.y : (q == 2) ? s4.z : s4.w;
            int d = (q == 0) ? d4.x : (q == 1) ? d4.y : (q == 2) ? d4.z : d4.w;
            int pos = atomicAdd(&g_count[d], 1);
            if (pos < CAP) {
                g_bucket[d * CAP + pos] = s;
            } else {
                int o = atomicAdd(&g_over, 1);
                if (o < OVF_MAX) { g_osrc[o] = s; g_odst[o] = d; }
            }
        }
    }
}

// ---------------------------------------------------------------------------
// Kernel C: per-node reduce. 8 threads/node; each thread owns 8 columns.
// Neighbor rows gathered from fp16 y16 (16B per thread per edge), self term
// and output in fp32. Unroll-4 on edges for MLP. Overflow folded inline.
// ---------------------------------------------------------------------------
__device__ __forceinline__ void add_row16(const uint4& u, float2* acc) {
    const __half2* hp = reinterpret_cast<const __half2*>(&u);
    #pragma unroll
    for (int q = 0; q < 4; q++) {
        float2 f = __half22float2(hp[q]);
        acc[q].x += f.x;
        acc[q].y += f.y;
    }
}

__global__ __launch_bounds__(256) void reduce_kernel(const float* __restrict__ eps,
                                                     float* __restrict__ out) {
    int tid  = threadIdx.x;
    int node = blockIdx.x * 32 + (tid >> 3);
    int j    = tid & 7;                 // columns [8j, 8j+8)
    if (node >= N_NODES) return;

    int deg_raw = g_count[node];
    int deg = deg_raw > CAP ? CAP : deg_raw;
    const int* bk = g_bucket + (size_t)node * CAP;

    float2 acc[4];
    #pragma unroll
    for (int q = 0; q < 4; q++) acc[q] = make_float2(0.f, 0.f);

    int k = 0;
    for (; k + 3 < deg; k += 4) {
        int s0 = __ldg(bk + k);
        int s1 = __ldg(bk + k + 1);
        int s2 = __ldg(bk + k + 2);
        int s3 = __ldg(bk + k + 3);
        uint4 u0 = __ldg(g_y16 + (size_t)s0 * (F / 8) + j);
        uint4 u1 = __ldg(g_y16 + (size_t)s1 * (F / 8) + j);
        uint4 u2 = __ldg(g_y16 + (size_t)s2 * (F / 8) + j);
        uint4 u3 = __ldg(g_y16 + (size_t)s3 * (F / 8) + j);
        add_row16(u0, acc);
        add_row16(u1, acc);
        add_row16(u2, acc);
        add_row16(u3, acc);
    }
    for (; k < deg; k++) {
        int s0 = __ldg(bk + k);
        uint4 u0 = __ldg(g_y16 + (size_t)s0 * (F / 8) + j);
        add_row16(u0, acc);
    }

    if (deg_raw > CAP) {   // essentially never taken
        int ov = g_over; if (ov > OVF_MAX) ov = OVF_MAX;
        for (int i = 0; i < ov; i++) {
            if (g_odst[i] == node) {
                uint4 u0 = __ldg(g_y16 + (size_t)g_osrc[i] * (F / 8) + j);
                add_row16(u0, acc);
            }
        }
    }

    float e1 = 1.0f + __ldg(eps);
    const float4* yd = reinterpret_cast<const float4*>(g_y + (size_t)node * F);
    float4 ya = __ldg(yd + j * 2);
    float4 yb = __ldg(yd + j * 2 + 1);
    float4 ca = reinterpret_cast<const float4*>(g_c)[j * 2];
    float4 cb = reinterpret_cast<const float4*>(g_c)[j * 2 + 1];

    float4 oa, ob;
    oa.x = acc[0].x + e1 * ya.x + ca.x;
    oa.y = acc[0].y + e1 * ya.y + ca.y;
    oa.z = acc[1].x + e1 * ya.z + ca.z;
    oa.w = acc[1].y + e1 * ya.w + ca.w;
    ob.x = acc[2].x + e1 * yb.x + cb.x;
    ob.y = acc[2].y + e1 * yb.y + cb.y;
    ob.z = acc[3].x + e1 * yb.z + cb.z;
    ob.w = acc[3].y + e1 * yb.w + cb.w;

    float4* orow = reinterpret_cast<float4*>(out + (size_t)node * F);
    orow[j * 2]     = oa;
    orow[j * 2 + 1] = ob;
}

// ---------------------------------------------------------------------------
extern "C" void kernel_launch(void* const* d_in, const int* in_sizes, int n_in,
                              void* d_out, int out_size) {
    const float* x   = (const float*)d_in[0];
    const float* W1  = (const float*)d_in[1];
    const float* b1  = (const float*)d_in[2];
    const float* W2  = (const float*)d_in[3];
    const float* b2  = (const float*)d_in[4];
    const float* eps = (const float*)d_in[5];
    const int*   src = (const int*)d_in[6];
    const int*   dst = (const int*)d_in[7];
    float* out = (float*)d_out;

    prep_kernel<<<17 + PREP_ZBLK, 256>>>(W1, b1, W2, b2);
    mid_kernel<<<GEMM_BLOCKS + FILL_BLOCKS, 256>>>(x, src, dst);
    reduce_kernel<<<(N_NODES + 31) / 32, 256>>>(eps, out);
}